// round 14
// baseline (speedup 1.0000x reference)
#include <cuda_runtime.h>
#include <cuda_fp16.h>

// ---------------------------------------------------------------------------
// Problem constants
// ---------------------------------------------------------------------------
#define NTOK 4096
#define CB   32
#define CIN  64
#define BATCH 2

#define QT     64                      // queries per block (4 warps x 16 rows)
#define NT     128                     // attn threads
#define KTILE  64
#define SPLITS 4
#define KTILES (NTOK / SPLITS / KTILE) // 16
#define KP     40
#define KPB    80

// attn dynamic SMEM layout (bytes)
#define OFF_QH   0                     // 64 rows x 80B = 5120
#define OFF_QL   5120
#define OFF_BUF  10240
#define BUF_SZ   10240                 // KH 5120 + VH 5120
#define BKH      0
#define BVH      5120
#define SMEM_BYTES (OFF_BUF + 2 * BUF_SZ)   // 30720 (x4 blocks/SM = 120KB)

// proj tiling
#define PROWS 64
#define PWP   72
#define NPROJ 96
#define WELEM (NPROJ * PWP)

// ---------------------------------------------------------------------------
// Scratch (no cudaMalloc allowed)
// ---------------------------------------------------------------------------
__device__ __align__(16) __half g_gh[BATCH * NTOK * CB];
__device__ __align__(16) __half g_gl[BATCH * NTOK * CB];
__device__ __align__(16) __half g_fh[BATCH * NTOK * CB];
__device__ __align__(16) __half g_hh[BATCH * NTOK * CB];
__device__ __align__(16) __half g_wh[WELEM];
__device__ __align__(16) __half g_wl[WELEM];
__device__ __align__(16) float g_part[SPLITS][BATCH * NTOK * CB];
__device__ __align__(16) float g_m[SPLITS][BATCH * NTOK];
__device__ __align__(16) float g_l[SPLITS][BATCH * NTOK];

// ---------------------------------------------------------------------------
// Helpers
// ---------------------------------------------------------------------------
__device__ __forceinline__ unsigned smem_u32(const void* p) {
    unsigned a;
    asm("{ .reg .u64 t; cvta.to.shared.u64 t, %1; cvt.u32.u64 %0, t; }"
        : "=r"(a) : "l"(p));
    return a;
}
__device__ __forceinline__ void cp16(unsigned dst, const void* src) {
    asm volatile("cp.async.cg.shared.global [%0], [%1], 16;"
                 :: "r"(dst), "l"(src) : "memory");
}
#define CP_COMMIT() asm volatile("cp.async.commit_group;" ::: "memory")
#define CP_WAIT1()  asm volatile("cp.async.wait_group 1;" ::: "memory")
#define CP_WAIT0()  asm volatile("cp.async.wait_group 0;" ::: "memory")

#define LDMX4(r, a) \
    asm volatile("ldmatrix.sync.aligned.m8n8.x4.shared.b16 {%0,%1,%2,%3}, [%4];" \
        : "=r"((r)[0]), "=r"((r)[1]), "=r"((r)[2]), "=r"((r)[3]) : "r"(a))
#define LDMX4T(r, a) \
    asm volatile("ldmatrix.sync.aligned.m8n8.x4.trans.shared.b16 {%0,%1,%2,%3}, [%4];" \
        : "=r"((r)[0]), "=r"((r)[1]), "=r"((r)[2]), "=r"((r)[3]) : "r"(a))

__device__ __forceinline__ void mma16816(float* d, const unsigned* a, const unsigned* b) {
    asm volatile(
        "mma.sync.aligned.m16n8k16.row.col.f32.f16.f16.f32 "
        "{%0,%1,%2,%3}, {%4,%5,%6,%7}, {%8,%9}, {%0,%1,%2,%3};"
        : "+f"(d[0]), "+f"(d[1]), "+f"(d[2]), "+f"(d[3])
        : "r"(a[0]), "r"(a[1]), "r"(a[2]), "r"(a[3]), "r"(b[0]), "r"(b[1]));
}

__device__ __forceinline__ void cvt_pair(float f0, float f1, unsigned& hi, unsigned& lo) {
    __half2 h = __floats2half2_rn(f0, f1);
    float r0 = f0 - __low2float(h);
    float r1 = f1 - __high2float(h);
    __half2 l = __floats2half2_rn(r0, r1);
    hi = *(unsigned*)&h;
    lo = *(unsigned*)&l;
}
__device__ __forceinline__ void cvt1(float f, __half& h, __half& l) {
    h = __float2half_rn(f);
    l = __float2half_rn(f - __half2float(h));
}

// ---------------------------------------------------------------------------
// Kernel 0: W split/transpose, once per launch
// ---------------------------------------------------------------------------
__global__ __launch_bounds__(256) void wprep_kernel(
    const float* __restrict__ Wf,
    const float* __restrict__ Wg,
    const float* __restrict__ Wh)
{
    int idx = blockIdx.x * blockDim.x + threadIdx.x;   // [0, 6144)
    int cb = idx >> 6;
    int k  = idx & 63;
    int p  = cb >> 5;
    int c  = cb & 31;
    const float* Ws = (p == 0) ? Wf : (p == 1) ? Wg : Wh;
    float v = Ws[k * CB + c];
    __half h, l;
    cvt1(v, h, l);
    g_wh[cb * PWP + k] = h;
    g_wl[cb * PWP + k] = l;
}

// ---------------------------------------------------------------------------
// Kernel 1: projections GEMM (unchanged from R13 — passing at 7.5us)
// ---------------------------------------------------------------------------
__global__ __launch_bounds__(128) void proj_mma_kernel(
    const float* __restrict__ x,
    const float* __restrict__ bf, const float* __restrict__ bg,
    const float* __restrict__ bh)
{
    __shared__ __half sXh[PROWS * PWP], sXl[PROWS * PWP];
    __shared__ __half sWh[WELEM], sWl[WELEM];

    const int t    = threadIdx.x;
    const int w    = t >> 5;
    const int lane = t & 31;
    const int row0 = blockIdx.x * PROWS;

    {
        const unsigned dWh = smem_u32(sWh);
        const unsigned dWl = smem_u32(sWl);
        const char* sh = (const char*)g_wh;
        const char* sl = (const char*)g_wl;
        for (int i = t; i < 864; i += 128) {
            cp16(dWh + i * 16, sh + i * 16);
            cp16(dWl + i * 16, sl + i * 16);
        }
        CP_COMMIT();
    }

    {
        int r = t >> 1, half = t & 1;
        const float4* src = (const float4*)(x + (size_t)(row0 + r) * CIN + half * 32);
        int e = r * PWP + half * 32;
#pragma unroll
        for (int i = 0; i < 8; i++) {
            float4 v = src[i];
            unsigned h0, l0, h1, l1;
            cvt_pair(v.x, v.y, h0, l0);
            cvt_pair(v.z, v.w, h1, l1);
            *(uint2*)(sXh + e + i * 4) = make_uint2(h0, h1);
            *(uint2*)(sXl + e + i * 4) = make_uint2(l0, l1);
        }
    }
    CP_WAIT0();
    __syncthreads();

    unsigned ah[4][4], al[4][4];
    {
        unsigned xa = smem_u32(sXh) + (w * 16 + (lane & 15)) * (PWP * 2) + (lane >> 4) * 16;
        unsigned xb = smem_u32(sXl) + (w * 16 + (lane & 15)) * (PWP * 2) + (lane >> 4) * 16;
#pragma unroll
        for (int ks = 0; ks < 4; ks++) {
            LDMX4(ah[ks], xa + ks * 32);
            LDMX4(al[ks], xb + ks * 32);
        }
    }

    float d[12][4];
#pragma unroll
    for (int nt = 0; nt < 12; nt++) {
        d[nt][0] = d[nt][1] = d[nt][2] = d[nt][3] = 0.f;
        unsigned wbh = smem_u32(sWh) + (nt * 8 + (lane & 7)) * (PWP * 2) + (lane >> 3) * 16;
        unsigned wbl = smem_u32(sWl) + (nt * 8 + (lane & 7)) * (PWP * 2) + (lane >> 3) * 16;
        unsigned bh0[4], bh1[4], bl0[4], bl1[4];
        LDMX4(bh0, wbh);
        LDMX4(bh1, wbh + 64);
        LDMX4(bl0, wbl);
        LDMX4(bl1, wbl + 64);
        mma16816(d[nt], ah[0], bh0 + 0);
        mma16816(d[nt], ah[1], bh0 + 2);
        mma16816(d[nt], ah[2], bh1 + 0);
        mma16816(d[nt], ah[3], bh1 + 2);
        mma16816(d[nt], al[0], bh0 + 0);
        mma16816(d[nt], al[1], bh0 + 2);
        mma16816(d[nt], al[2], bh1 + 0);
        mma16816(d[nt], al[3], bh1 + 2);
        mma16816(d[nt], ah[0], bl0 + 0);
        mma16816(d[nt], ah[1], bl0 + 2);
        mma16816(d[nt], ah[2], bl1 + 0);
        mma16816(d[nt], ah[3], bl1 + 2);
    }

    {
        int r0 = row0 + w * 16 + (lane >> 2);
        int r1 = r0 + 8;
        __half* dh[3] = {g_fh, g_gh, g_hh};
        const float* bias[3] = {bf, bg, bh};
#pragma unroll
        for (int nt = 0; nt < 12; nt++) {
            const int p  = nt >> 2;
            int c  = (nt & 3) * 8 + (lane & 3) * 2;
            float b0 = bias[p][c], b1 = bias[p][c + 1];
            unsigned hi, lo;
            cvt_pair(d[nt][0] + b0, d[nt][1] + b1, hi, lo);
            *(unsigned*)(dh[p] + (size_t)r0 * CB + c) = hi;
            if (p == 1) *(unsigned*)(g_gl + (size_t)r0 * CB + c) = lo;
            cvt_pair(d[nt][2] + b0, d[nt][3] + b1, hi, lo);
            *(unsigned*)(dh[p] + (size_t)r1 * CB + c) = hi;
            if (p == 1) *(unsigned*)(g_gl + (size_t)r1 * CB + c) = lo;
        }
    }
}

// ---------------------------------------------------------------------------
// Kernel 2: flash attention — QT=64, 128 threads, 4 blocks/SM for balance.
// Per-warp structure identical to R11/R13 (bit-identical arithmetic).
// ---------------------------------------------------------------------------
__global__ __launch_bounds__(NT, 4) void attn_kernel()
{
    extern __shared__ __align__(16) unsigned char smem[];
    const unsigned sbase = smem_u32(smem);

    const int b  = blockIdx.y;
    const int q0 = blockIdx.x * QT;
    const int k0 = blockIdx.z * (NTOK / SPLITS);
    const int t  = threadIdx.x;
    const int w  = t >> 5;
    const int lane = t & 31;

    // staging: r = t>>1 (0..63), hf = t&1 (16-half)
    const int sr = t >> 1, shf = t & 1;
    const size_t qoff = (size_t)(b * NTOK + q0 + sr) * CB + shf * 16;
    const unsigned qdH = sbase + OFF_QH + sr * KPB + shf * 32;
    const unsigned qdL = sbase + OFF_QL + sr * KPB + shf * 32;

    cp16(qdH,      g_gh + qoff);
    cp16(qdH + 16, g_gh + qoff + 8);
    cp16(qdL,      g_gl + qoff);
    cp16(qdL + 16, g_gl + qoff + 8);
    {
        size_t goff = (size_t)(b * NTOK + k0 + sr) * CB + shf * 16;
        unsigned so = sbase + OFF_BUF + sr * KPB + shf * 32;
        cp16(so + BKH,      g_fh + goff);
        cp16(so + BKH + 16, g_fh + goff + 8);
        cp16(so + BVH,      g_hh + goff);
        cp16(so + BVH + 16, g_hh + goff + 8);
    }
    CP_COMMIT();
    {
        size_t goff = (size_t)(b * NTOK + k0 + KTILE + sr) * CB + shf * 16;
        unsigned so = sbase + OFF_BUF + BUF_SZ + sr * KPB + shf * 32;
        cp16(so + BKH,      g_fh + goff);
        cp16(so + BKH + 16, g_fh + goff + 8);
        cp16(so + BVH,      g_hh + goff);
        cp16(so + BVH + 16, g_hh + goff + 8);
    }
    CP_COMMIT();

    unsigned qh[2][4], ql[2][4];
    float m0 = -1e30f, m1 = -1e30f, l0 = 0.f, l1 = 0.f;
    float o[4][4];
#pragma unroll
    for (int nn = 0; nn < 4; nn++)
#pragma unroll
        for (int j = 0; j < 4; j++) o[nn][j] = 0.f;

    for (int kt = 0; kt < KTILES; kt++) {
        CP_WAIT1();
        __syncthreads();

        if (kt == 0) {
            unsigned qa = sbase + OFF_QH + (w * 16 + (lane & 15)) * KPB + (lane >> 4) * 16;
            unsigned qb = sbase + OFF_QL + (w * 16 + (lane & 15)) * KPB + (lane >> 4) * 16;
            LDMX4(qh[0], qa);
            LDMX4(qh[1], qa + 32);
            LDMX4(ql[0], qb);
            LDMX4(ql[1], qb + 32);
        }

        const unsigned bufb = sbase + OFF_BUF + (kt & 1) * BUF_SZ;
        const unsigned kaddr_h = bufb + BKH + (lane & 7) * KPB + (lane >> 3) * 16;
        const unsigned vbase_h = bufb + BVH + lane * KPB;

        float s[8][4];
#pragma unroll
        for (int n = 0; n < 8; n++) {
            s[n][0] = s[n][1] = s[n][2] = s[n][3] = 0.f;
            unsigned kh[4];
            LDMX4(kh, kaddr_h + n * 8 * KPB);
            mma16816(s[n], qh[0], kh + 0);
            mma16816(s[n], qh[1], kh + 2);
            mma16816(s[n], ql[0], kh + 0);
            mma16816(s[n], ql[1], kh + 2);
        }

        unsigned vh0[4][4];
#pragma unroll
        for (int nn = 0; nn < 4; nn++)
            LDMX4T(vh0[nn], vbase_h + nn * 16);

        float r0 = -1e30f, r1 = -1e30f;
#pragma unroll
        for (int n = 0; n < 8; n++) {
            r0 = fmaxf(r0, fmaxf(s[n][0], s[n][1]));
            r1 = fmaxf(r1, fmaxf(s[n][2], s[n][3]));
        }
        r0 = fmaxf(r0, __shfl_xor_sync(0xffffffffu, r0, 1));
        r0 = fmaxf(r0, __shfl_xor_sync(0xffffffffu, r0, 2));
        r1 = fmaxf(r1, __shfl_xor_sync(0xffffffffu, r1, 1));
        r1 = fmaxf(r1, __shfl_xor_sync(0xffffffffu, r1, 2));
        float mn0 = fmaxf(m0, r0), mn1 = fmaxf(m1, r1);
        float al0 = __expf(m0 - mn0), al1 = __expf(m1 - mn1);

        float ps0 = 0.f, ps1 = 0.f;
        unsigned ph[4][4];
#pragma unroll
        for (int n = 0; n < 8; n++) {
            float p0 = __expf(s[n][0] - mn0);
            float p1 = __expf(s[n][1] - mn0);
            float p2 = __expf(s[n][2] - mn1);
            float p3 = __expf(s[n][3] - mn1);
            ps0 += p0 + p1;  ps1 += p2 + p3;
            int kk = n >> 1, hset = (n & 1) * 2;
            __half2 hp0 = __floats2half2_rn(p0, p1);
            __half2 hp1 = __floats2half2_rn(p2, p3);
            ph[kk][hset + 0] = *(unsigned*)&hp0;
            ph[kk][hset + 1] = *(unsigned*)&hp1;
        }
        ps0 += __shfl_xor_sync(0xffffffffu, ps0, 1);
        ps0 += __shfl_xor_sync(0xffffffffu, ps0, 2);
        ps1 += __shfl_xor_sync(0xffffffffu, ps1, 1);
        ps1 += __shfl_xor_sync(0xffffffffu, ps1, 2);
        l0 = l0 * al0 + ps0;  l1 = l1 * al1 + ps1;
        m0 = mn0;  m1 = mn1;

#pragma unroll
        for (int nn = 0; nn < 4; nn++) {
            o[nn][0] *= al0; o[nn][1] *= al0;
            o[nn][2] *= al1; o[nn][3] *= al1;
        }

#pragma unroll
        for (int nn = 0; nn < 4; nn++) {
            mma16816(o[nn], ph[0], vh0[nn] + 0);
            mma16816(o[nn], ph[1], vh0[nn] + 2);
        }
#pragma unroll
        for (int nn = 0; nn < 4; nn++) {
            unsigned vh[4];
            LDMX4T(vh, vbase_h + (unsigned)(32 * KPB + nn * 16));
            mma16816(o[nn], ph[2], vh + 0);
            mma16816(o[nn], ph[3], vh + 2);
        }

        __syncthreads();
        if (kt + 2 < KTILES) {
            size_t goff = (size_t)(b * NTOK + k0 + (kt + 2) * KTILE + sr) * CB + shf * 16;
            unsigned so = bufb + sr * KPB + shf * 32;
            cp16(so + BKH,      g_fh + goff);
            cp16(so + BKH + 16, g_fh + goff + 8);
            cp16(so + BVH,      g_hh + goff);
            cp16(so + BVH + 16, g_hh + goff + 8);
        }
        CP_COMMIT();
    }

    {
        int z = blockIdx.z;
        int r = lane >> 2;
        int c = (lane & 3) * 2;
        int grow0 = b * NTOK + q0 + w * 16 + r;
        int grow1 = grow0 + 8;
        if ((lane & 3) == 0) {
            g_m[z][grow0] = m0;  g_l[z][grow0] = l0;
            g_m[z][grow1] = m1;  g_l[z][grow1] = l1;
        }
#pragma unroll
        for (int nn = 0; nn < 4; nn++) {
            *(float2*)&g_part[z][(size_t)grow0 * CB + nn * 8 + c] = make_float2(o[nn][0], o[nn][1]);
            *(float2*)&g_part[z][(size_t)grow1 * CB + nn * 8 + c] = make_float2(o[nn][2], o[nn][3]);
        }
    }
}

// ---------------------------------------------------------------------------
// Kernel 3: fused combine(4 splits) + output projection + residual (unchanged)
// ---------------------------------------------------------------------------
__global__ __launch_bounds__(256) void outc_kernel(
    const float* __restrict__ x,
    const float* __restrict__ Wo, const float* __restrict__ bo,
    const float* __restrict__ gamma,
    float* __restrict__ out)
{
    int idx = blockIdx.x * blockDim.x + threadIdx.x;
    int row = idx >> 5;
    int sub = idx & 31;
    int c4  = (sub & 15) * 4;
    int kh  = sub >> 4;

    float mz[SPLITS], lz[SPLITS];
    float M = -1e30f;
#pragma unroll
    for (int z = 0; z < SPLITS; z++) {
        mz[z] = g_m[z][row];
        lz[z] = g_l[z][row];
        M = fmaxf(M, mz[z]);
    }
    float wz[SPLITS];
    float denom = 0.f;
#pragma unroll
    for (int z = 0; z < SPLITS; z++) {
        wz[z] = __expf(mz[z] - M);
        denom += lz[z] * wz[z];
    }
    float inv = 1.0f / denom;
#pragma unroll
    for (int z = 0; z < SPLITS; z++) wz[z] *= inv;

    float4 o = make_float4(0.f, 0.f, 0.f, 0.f);
#pragma unroll
    for (int j4 = 0; j4 < 4; j4++) {
        float bs[4] = {0.f, 0.f, 0.f, 0.f};
#pragma unroll
        for (int z = 0; z < SPLITS; z++) {
            float4 a = *(const float4*)(&g_part[z][0] + (size_t)row * CB + kh * 16 + j4 * 4);
            bs[0] += a.x * wz[z];
            bs[1] += a.y * wz[z];
            bs[2] += a.z * wz[z];
            bs[3] += a.w * wz[z];
        }
#pragma unroll
        for (int j = 0; j < 4; j++) {
            float4 wv = *(const float4*)(Wo + (kh * 16 + j4 * 4 + j) * CIN + c4);
            o.x = fmaf(bs[j], wv.x, o.x);
            o.y = fmaf(bs[j], wv.y, o.y);
            o.z = fmaf(bs[j], wv.z, o.z);
            o.w = fmaf(bs[j], wv.w, o.w);
        }
    }
    o.x += __shfl_xor_sync(0xffffffffu, o.x, 16);
    o.y += __shfl_xor_sync(0xffffffffu, o.y, 16);
    o.z += __shfl_xor_sync(0xffffffffu, o.z, 16);
    o.w += __shfl_xor_sync(0xffffffffu, o.w, 16);

    if (kh == 0) {
        float gm = gamma[0];
        float4 bv = *(const float4*)(bo + c4);
        float4 xv = *(const float4*)(x + (size_t)row * CIN + c4);
        float4 r;
        r.x = xv.x + gm * (o.x + bv.x);
        r.y = xv.y + gm * (o.y + bv.y);
        r.z = xv.z + gm * (o.z + bv.z);
        r.w = xv.w + gm * (o.w + bv.w);
        *(float4*)(out + (size_t)row * CIN + c4) = r;
    }
}

// ---------------------------------------------------------------------------
extern "C" void kernel_launch(void* const* d_in, const int* in_sizes, int n_in,
                              void* d_out, int out_size)
{
    const float* x     = (const float*)d_in[0];
    const float* Wf    = (const float*)d_in[1];
    const float* bf    = (const float*)d_in[2];
    const float* Wg    = (const float*)d_in[3];
    const float* bg    = (const float*)d_in[4];
    const float* Wh    = (const float*)d_in[5];
    const float* bh    = (const float*)d_in[6];
    const float* Wo    = (const float*)d_in[7];
    const float* bo    = (const float*)d_in[8];
    const float* gamma = (const float*)d_in[9];
    float* out = (float*)d_out;
    (void)in_sizes; (void)n_in; (void)out_size;

    cudaFuncSetAttribute(attn_kernel,
                         cudaFuncAttributeMaxDynamicSharedMemorySize, SMEM_BYTES);

    wprep_kernel<<<24, 256>>>(Wf, Wg, Wh);

    proj_mma_kernel<<<BATCH * NTOK / PROWS, 128>>>(x, bf, bg, bh);

    dim3 agrid(NTOK / QT, BATCH, SPLITS);
    attn_kernel<<<agrid, NT, SMEM_BYTES>>>();

    outc_kernel<<<BATCH * NTOK * 32 / 256, 256>>>(x, Wo, bo, gamma, out);
}

// round 15
// speedup vs baseline: 1.0442x; 1.0442x over previous
#include <cuda_runtime.h>
#include <cuda_fp16.h>

// ---------------------------------------------------------------------------
// Problem constants
// ---------------------------------------------------------------------------
#define NTOK 4096
#define CB   32
#define CIN  64
#define BATCH 2

#define QT     128                     // queries per block (8 warps x 16 rows)
#define NT     256
#define KTILE  64
#define SPLITS 4
#define KTILES (NTOK / SPLITS / KTILE) // 16
#define KP     40
#define KPB    80

// attn dynamic SMEM layout (bytes): Q hi/lo + 3 K/V buffers
#define OFF_QH   0
#define OFF_QL   10240
#define OFF_BUF  20480
#define BUF_SZ   10240                 // KH 5120 + VH 5120
#define BKH      0
#define BVH      5120
#define SMEM_BYTES (OFF_BUF + 3 * BUF_SZ)   // 51200 (x2 blocks/SM = 100KB)

// proj tiling
#define PROWS 64
#define PWP   72
#define NPROJ 96
#define WELEM (NPROJ * PWP)

// ---------------------------------------------------------------------------
// Scratch (no cudaMalloc allowed)
// ---------------------------------------------------------------------------
__device__ __align__(16) __half g_gh[BATCH * NTOK * CB];
__device__ __align__(16) __half g_gl[BATCH * NTOK * CB];
__device__ __align__(16) __half g_fh[BATCH * NTOK * CB];
__device__ __align__(16) __half g_hh[BATCH * NTOK * CB];
__device__ __align__(16) __half g_wh[WELEM];
__device__ __align__(16) __half g_wl[WELEM];
__device__ __align__(16) float g_part[SPLITS][BATCH * NTOK * CB];
__device__ __align__(16) float g_m[SPLITS][BATCH * NTOK];
__device__ __align__(16) float g_l[SPLITS][BATCH * NTOK];

// ---------------------------------------------------------------------------
// Helpers
// ---------------------------------------------------------------------------
__device__ __forceinline__ unsigned smem_u32(const void* p) {
    unsigned a;
    asm("{ .reg .u64 t; cvta.to.shared.u64 t, %1; cvt.u32.u64 %0, t; }"
        : "=r"(a) : "l"(p));
    return a;
}
__device__ __forceinline__ void cp16(unsigned dst, const void* src) {
    asm volatile("cp.async.cg.shared.global [%0], [%1], 16;"
                 :: "r"(dst), "l"(src) : "memory");
}
#define CP_COMMIT() asm volatile("cp.async.commit_group;" ::: "memory")
#define CP_WAIT1()  asm volatile("cp.async.wait_group 1;" ::: "memory")
#define CP_WAIT0()  asm volatile("cp.async.wait_group 0;" ::: "memory")

#define LDMX4(r, a) \
    asm volatile("ldmatrix.sync.aligned.m8n8.x4.shared.b16 {%0,%1,%2,%3}, [%4];" \
        : "=r"((r)[0]), "=r"((r)[1]), "=r"((r)[2]), "=r"((r)[3]) : "r"(a))
#define LDMX4T(r, a) \
    asm volatile("ldmatrix.sync.aligned.m8n8.x4.trans.shared.b16 {%0,%1,%2,%3}, [%4];" \
        : "=r"((r)[0]), "=r"((r)[1]), "=r"((r)[2]), "=r"((r)[3]) : "r"(a))

__device__ __forceinline__ void mma16816(float* d, const unsigned* a, const unsigned* b) {
    asm volatile(
        "mma.sync.aligned.m16n8k16.row.col.f32.f16.f16.f32 "
        "{%0,%1,%2,%3}, {%4,%5,%6,%7}, {%8,%9}, {%0,%1,%2,%3};"
        : "+f"(d[0]), "+f"(d[1]), "+f"(d[2]), "+f"(d[3])
        : "r"(a[0]), "r"(a[1]), "r"(a[2]), "r"(a[3]), "r"(b[0]), "r"(b[1]));
}

__device__ __forceinline__ void cvt_pair(float f0, float f1, unsigned& hi, unsigned& lo) {
    __half2 h = __floats2half2_rn(f0, f1);
    float r0 = f0 - __low2float(h);
    float r1 = f1 - __high2float(h);
    __half2 l = __floats2half2_rn(r0, r1);
    hi = *(unsigned*)&h;
    lo = *(unsigned*)&l;
}
__device__ __forceinline__ void cvt1(float f, __half& h, __half& l) {
    h = __float2half_rn(f);
    l = __float2half_rn(f - __half2float(h));
}

// ---------------------------------------------------------------------------
// Kernel 0: W split/transpose, once per launch
// ---------------------------------------------------------------------------
__global__ __launch_bounds__(256) void wprep_kernel(
    const float* __restrict__ Wf,
    const float* __restrict__ Wg,
    const float* __restrict__ Wh)
{
    int idx = blockIdx.x * blockDim.x + threadIdx.x;
    int cb = idx >> 6;
    int k  = idx & 63;
    int p  = cb >> 5;
    int c  = cb & 31;
    const float* Ws = (p == 0) ? Wf : (p == 1) ? Wg : Wh;
    float v = Ws[k * CB + c];
    __half h, l;
    cvt1(v, h, l);
    g_wh[cb * PWP + k] = h;
    g_wl[cb * PWP + k] = l;
}

// ---------------------------------------------------------------------------
// Kernel 1: projections GEMM (unchanged — measured 7.5us)
// ---------------------------------------------------------------------------
__global__ __launch_bounds__(128) void proj_mma_kernel(
    const float* __restrict__ x,
    const float* __restrict__ bf, const float* __restrict__ bg,
    const float* __restrict__ bh)
{
    __shared__ __half sXh[PROWS * PWP], sXl[PROWS * PWP];
    __shared__ __half sWh[WELEM], sWl[WELEM];

    const int t    = threadIdx.x;
    const int w    = t >> 5;
    const int lane = t & 31;
    const int row0 = blockIdx.x * PROWS;

    {
        const unsigned dWh = smem_u32(sWh);
        const unsigned dWl = smem_u32(sWl);
        const char* sh = (const char*)g_wh;
        const char* sl = (const char*)g_wl;
        for (int i = t; i < 864; i += 128) {
            cp16(dWh + i * 16, sh + i * 16);
            cp16(dWl + i * 16, sl + i * 16);
        }
        CP_COMMIT();
    }

    {
        int r = t >> 1, half = t & 1;
        const float4* src = (const float4*)(x + (size_t)(row0 + r) * CIN + half * 32);
        int e = r * PWP + half * 32;
#pragma unroll
        for (int i = 0; i < 8; i++) {
            float4 v = src[i];
            unsigned h0, l0, h1, l1;
            cvt_pair(v.x, v.y, h0, l0);
            cvt_pair(v.z, v.w, h1, l1);
            *(uint2*)(sXh + e + i * 4) = make_uint2(h0, h1);
            *(uint2*)(sXl + e + i * 4) = make_uint2(l0, l1);
        }
    }
    CP_WAIT0();
    __syncthreads();

    unsigned ah[4][4], al[4][4];
    {
        unsigned xa = smem_u32(sXh) + (w * 16 + (lane & 15)) * (PWP * 2) + (lane >> 4) * 16;
        unsigned xb = smem_u32(sXl) + (w * 16 + (lane & 15)) * (PWP * 2) + (lane >> 4) * 16;
#pragma unroll
        for (int ks = 0; ks < 4; ks++) {
            LDMX4(ah[ks], xa + ks * 32);
            LDMX4(al[ks], xb + ks * 32);
        }
    }

    float d[12][4];
#pragma unroll
    for (int nt = 0; nt < 12; nt++) {
        d[nt][0] = d[nt][1] = d[nt][2] = d[nt][3] = 0.f;
        unsigned wbh = smem_u32(sWh) + (nt * 8 + (lane & 7)) * (PWP * 2) + (lane >> 3) * 16;
        unsigned wbl = smem_u32(sWl) + (nt * 8 + (lane & 7)) * (PWP * 2) + (lane >> 3) * 16;
        unsigned bh0[4], bh1[4], bl0[4], bl1[4];
        LDMX4(bh0, wbh);
        LDMX4(bh1, wbh + 64);
        LDMX4(bl0, wbl);
        LDMX4(bl1, wbl + 64);
        mma16816(d[nt], ah[0], bh0 + 0);
        mma16816(d[nt], ah[1], bh0 + 2);
        mma16816(d[nt], ah[2], bh1 + 0);
        mma16816(d[nt], ah[3], bh1 + 2);
        mma16816(d[nt], al[0], bh0 + 0);
        mma16816(d[nt], al[1], bh0 + 2);
        mma16816(d[nt], al[2], bh1 + 0);
        mma16816(d[nt], al[3], bh1 + 2);
        mma16816(d[nt], ah[0], bl0 + 0);
        mma16816(d[nt], ah[1], bl0 + 2);
        mma16816(d[nt], ah[2], bl1 + 0);
        mma16816(d[nt], ah[3], bl1 + 2);
    }

    {
        int r0 = row0 + w * 16 + (lane >> 2);
        int r1 = r0 + 8;
        __half* dh[3] = {g_fh, g_gh, g_hh};
        const float* bias[3] = {bf, bg, bh};
#pragma unroll
        for (int nt = 0; nt < 12; nt++) {
            const int p  = nt >> 2;
            int c  = (nt & 3) * 8 + (lane & 3) * 2;
            float b0 = bias[p][c], b1 = bias[p][c + 1];
            unsigned hi, lo;
            cvt_pair(d[nt][0] + b0, d[nt][1] + b1, hi, lo);
            *(unsigned*)(dh[p] + (size_t)r0 * CB + c) = hi;
            if (p == 1) *(unsigned*)(g_gl + (size_t)r0 * CB + c) = lo;
            cvt_pair(d[nt][2] + b0, d[nt][3] + b1, hi, lo);
            *(unsigned*)(dh[p] + (size_t)r1 * CB + c) = hi;
            if (p == 1) *(unsigned*)(g_gl + (size_t)r1 * CB + c) = lo;
        }
    }
}

// ---------------------------------------------------------------------------
// Kernel 2: flash attention — QT=128, triple-buffered K/V, ONE barrier/tile,
// prefetch issued at iteration top. Arithmetic identical to R11.
// ---------------------------------------------------------------------------
__global__ __launch_bounds__(NT, 2) void attn_kernel()
{
    extern __shared__ __align__(16) unsigned char smem[];
    const unsigned sbase = smem_u32(smem);

    const int b  = blockIdx.y;
    const int q0 = blockIdx.x * QT;
    const int k0 = blockIdx.z * (NTOK / SPLITS);
    const int t  = threadIdx.x;
    const int w  = t >> 5;
    const int lane = t & 31;

    const int qrow = t >> 1, qhalf = t & 1;
    const int krow = t >> 2, kq = t & 3;
    const size_t qoff = (size_t)(b * NTOK + q0 + qrow) * CB + qhalf * 16;
    const unsigned qdH = sbase + OFF_QH + qrow * KPB + qhalf * 32;
    const unsigned qdL = sbase + OFF_QL + qrow * KPB + qhalf * 32;

    // Prologue: Q + tile0 (group), tile1 (group)
    cp16(qdH,      g_gh + qoff);
    cp16(qdH + 16, g_gh + qoff + 8);
    cp16(qdL,      g_gl + qoff);
    cp16(qdL + 16, g_gl + qoff + 8);
    {
        size_t goff = (size_t)(b * NTOK + k0 + krow) * CB + kq * 8;
        unsigned so = sbase + OFF_BUF + krow * KPB + kq * 16;
        cp16(so + BKH, g_fh + goff);
        cp16(so + BVH, g_hh + goff);
    }
    CP_COMMIT();
    {
        size_t goff = (size_t)(b * NTOK + k0 + KTILE + krow) * CB + kq * 8;
        unsigned so = sbase + OFF_BUF + BUF_SZ + krow * KPB + kq * 16;
        cp16(so + BKH, g_fh + goff);
        cp16(so + BVH, g_hh + goff);
    }
    CP_COMMIT();

    unsigned qh[2][4], ql[2][4];
    float m0 = -1e30f, m1 = -1e30f, l0 = 0.f, l1 = 0.f;
    float o[4][4];
#pragma unroll
    for (int nn = 0; nn < 4; nn++)
#pragma unroll
        for (int j = 0; j < 4; j++) o[nn][j] = 0.f;

    int bufr = 0;   // buffer being read this tile (rotates 0,1,2)
    for (int kt = 0; kt < KTILES; kt++) {
        CP_WAIT1();          // tile kt data complete
        __syncthreads();     // single barrier: staging visible AND prior-iter
                             // readers of buf[(kt+2)%3] are done

        // ---- Prefetch tile kt+2 into the idle buffer (overlaps compute) --
        {
            int bufw = bufr + 2;  if (bufw >= 3) bufw -= 3;
            if (kt + 2 < KTILES) {
                size_t goff = (size_t)(b * NTOK + k0 + (kt + 2) * KTILE + krow) * CB + kq * 8;
                unsigned so = sbase + OFF_BUF + bufw * BUF_SZ + krow * KPB + kq * 16;
                cp16(so + BKH, g_fh + goff);
                cp16(so + BVH, g_hh + goff);
            }
            CP_COMMIT();     // always commit: wait accounting stays exact
        }

        if (kt == 0) {
            unsigned qa = sbase + OFF_QH + (w * 16 + (lane & 15)) * KPB + (lane >> 4) * 16;
            unsigned qb = sbase + OFF_QL + (w * 16 + (lane & 15)) * KPB + (lane >> 4) * 16;
            LDMX4(qh[0], qa);
            LDMX4(qh[1], qa + 32);
            LDMX4(ql[0], qb);
            LDMX4(ql[1], qb + 32);
        }

        const unsigned bufb = sbase + OFF_BUF + bufr * BUF_SZ;
        const unsigned kaddr_h = bufb + BKH + (lane & 7) * KPB + (lane >> 3) * 16;
        const unsigned vbase_h = bufb + BVH + lane * KPB;

        // ---- GEMM1 --------------------------------------------------------
        float s[8][4];
#pragma unroll
        for (int n = 0; n < 8; n++) {
            s[n][0] = s[n][1] = s[n][2] = s[n][3] = 0.f;
            unsigned kh[4];
            LDMX4(kh, kaddr_h + n * 8 * KPB);
            mma16816(s[n], qh[0], kh + 0);
            mma16816(s[n], qh[1], kh + 2);
            mma16816(s[n], ql[0], kh + 0);
            mma16816(s[n], ql[1], kh + 2);
        }

        unsigned vh0[4][4];
#pragma unroll
        for (int nn = 0; nn < 4; nn++)
            LDMX4T(vh0[nn], vbase_h + nn * 16);

        // ---- Online softmax ------------------------------------------------
        float r0 = -1e30f, r1 = -1e30f;
#pragma unroll
        for (int n = 0; n < 8; n++) {
            r0 = fmaxf(r0, fmaxf(s[n][0], s[n][1]));
            r1 = fmaxf(r1, fmaxf(s[n][2], s[n][3]));
        }
        r0 = fmaxf(r0, __shfl_xor_sync(0xffffffffu, r0, 1));
        r0 = fmaxf(r0, __shfl_xor_sync(0xffffffffu, r0, 2));
        r1 = fmaxf(r1, __shfl_xor_sync(0xffffffffu, r1, 1));
        r1 = fmaxf(r1, __shfl_xor_sync(0xffffffffu, r1, 2));
        float mn0 = fmaxf(m0, r0), mn1 = fmaxf(m1, r1);
        float al0 = __expf(m0 - mn0), al1 = __expf(m1 - mn1);

        float ps0 = 0.f, ps1 = 0.f;
        unsigned ph[4][4];
#pragma unroll
        for (int n = 0; n < 8; n++) {
            float p0 = __expf(s[n][0] - mn0);
            float p1 = __expf(s[n][1] - mn0);
            float p2 = __expf(s[n][2] - mn1);
            float p3 = __expf(s[n][3] - mn1);
            ps0 += p0 + p1;  ps1 += p2 + p3;
            int kk = n >> 1, hset = (n & 1) * 2;
            __half2 hp0 = __floats2half2_rn(p0, p1);
            __half2 hp1 = __floats2half2_rn(p2, p3);
            ph[kk][hset + 0] = *(unsigned*)&hp0;
            ph[kk][hset + 1] = *(unsigned*)&hp1;
        }
        ps0 += __shfl_xor_sync(0xffffffffu, ps0, 1);
        ps0 += __shfl_xor_sync(0xffffffffu, ps0, 2);
        ps1 += __shfl_xor_sync(0xffffffffu, ps1, 1);
        ps1 += __shfl_xor_sync(0xffffffffu, ps1, 2);
        l0 = l0 * al0 + ps0;  l1 = l1 * al1 + ps1;
        m0 = mn0;  m1 = mn1;

#pragma unroll
        for (int nn = 0; nn < 4; nn++) {
            o[nn][0] *= al0; o[nn][1] *= al0;
            o[nn][2] *= al1; o[nn][3] *= al1;
        }

        // ---- GEMM2 ----------------------------------------------------------
#pragma unroll
        for (int nn = 0; nn < 4; nn++) {
            mma16816(o[nn], ph[0], vh0[nn] + 0);
            mma16816(o[nn], ph[1], vh0[nn] + 2);
        }
#pragma unroll
        for (int nn = 0; nn < 4; nn++) {
            unsigned vh[4];
            LDMX4T(vh, vbase_h + (unsigned)(32 * KPB + nn * 16));
            mma16816(o[nn], ph[2], vh + 0);
            mma16816(o[nn], ph[3], vh + 2);
        }

        bufr++;  if (bufr == 3) bufr = 0;
    }

    // ---- Epilogue ----------------------------------------------------------
    {
        int z = blockIdx.z;
        int r = lane >> 2;
        int c = (lane & 3) * 2;
        int grow0 = b * NTOK + q0 + w * 16 + r;
        int grow1 = grow0 + 8;
        if ((lane & 3) == 0) {
            g_m[z][grow0] = m0;  g_l[z][grow0] = l0;
            g_m[z][grow1] = m1;  g_l[z][grow1] = l1;
        }
#pragma unroll
        for (int nn = 0; nn < 4; nn++) {
            *(float2*)&g_part[z][(size_t)grow0 * CB + nn * 8 + c] = make_float2(o[nn][0], o[nn][1]);
            *(float2*)&g_part[z][(size_t)grow1 * CB + nn * 8 + c] = make_float2(o[nn][2], o[nn][3]);
        }
    }
}

// ---------------------------------------------------------------------------
// Kernel 3: fused combine(4 splits) + output projection + residual (unchanged)
// ---------------------------------------------------------------------------
__global__ __launch_bounds__(256) void outc_kernel(
    const float* __restrict__ x,
    const float* __restrict__ Wo, const float* __restrict__ bo,
    const float* __restrict__ gamma,
    float* __restrict__ out)
{
    int idx = blockIdx.x * blockDim.x + threadIdx.x;
    int row = idx >> 5;
    int sub = idx & 31;
    int c4  = (sub & 15) * 4;
    int kh  = sub >> 4;

    float mz[SPLITS], lz[SPLITS];
    float M = -1e30f;
#pragma unroll
    for (int z = 0; z < SPLITS; z++) {
        mz[z] = g_m[z][row];
        lz[z] = g_l[z][row];
        M = fmaxf(M, mz[z]);
    }
    float wz[SPLITS];
    float denom = 0.f;
#pragma unroll
    for (int z = 0; z < SPLITS; z++) {
        wz[z] = __expf(mz[z] - M);
        denom += lz[z] * wz[z];
    }
    float inv = 1.0f / denom;
#pragma unroll
    for (int z = 0; z < SPLITS; z++) wz[z] *= inv;

    float4 o = make_float4(0.f, 0.f, 0.f, 0.f);
#pragma unroll
    for (int j4 = 0; j4 < 4; j4++) {
        float bs[4] = {0.f, 0.f, 0.f, 0.f};
#pragma unroll
        for (int z = 0; z < SPLITS; z++) {
            float4 a = *(const float4*)(&g_part[z][0] + (size_t)row * CB + kh * 16 + j4 * 4);
            bs[0] += a.x * wz[z];
            bs[1] += a.y * wz[z];
            bs[2] += a.z * wz[z];
            bs[3] += a.w * wz[z];
        }
#pragma unroll
        for (int j = 0; j < 4; j++) {
            float4 wv = *(const float4*)(Wo + (kh * 16 + j4 * 4 + j) * CIN + c4);
            o.x = fmaf(bs[j], wv.x, o.x);
            o.y = fmaf(bs[j], wv.y, o.y);
            o.z = fmaf(bs[j], wv.z, o.z);
            o.w = fmaf(bs[j], wv.w, o.w);
        }
    }
    o.x += __shfl_xor_sync(0xffffffffu, o.x, 16);
    o.y += __shfl_xor_sync(0xffffffffu, o.y, 16);
    o.z += __shfl_xor_sync(0xffffffffu, o.z, 16);
    o.w += __shfl_xor_sync(0xffffffffu, o.w, 16);

    if (kh == 0) {
        float gm = gamma[0];
        float4 bv = *(const float4*)(bo + c4);
        float4 xv = *(const float4*)(x + (size_t)row * CIN + c4);
        float4 r;
        r.x = xv.x + gm * (o.x + bv.x);
        r.y = xv.y + gm * (o.y + bv.y);
        r.z = xv.z + gm * (o.z + bv.z);
        r.w = xv.w + gm * (o.w + bv.w);
        *(float4*)(out + (size_t)row * CIN + c4) = r;
    }
}

// ---------------------------------------------------------------------------
extern "C" void kernel_launch(void* const* d_in, const int* in_sizes, int n_in,
                              void* d_out, int out_size)
{
    const float* x     = (const float*)d_in[0];
    const float* Wf    = (const float*)d_in[1];
    const float* bf    = (const float*)d_in[2];
    const float* Wg    = (const float*)d_in[3];
    const float* bg    = (const float*)d_in[4];
    const float* Wh    = (const float*)d_in[5];
    const float* bh    = (const float*)d_in[6];
    const float* Wo    = (const float*)d_in[7];
    const float* bo    = (const float*)d_in[8];
    const float* gamma = (const float*)d_in[9];
    float* out = (float*)d_out;
    (void)in_sizes; (void)n_in; (void)out_size;

    cudaFuncSetAttribute(attn_kernel,
                         cudaFuncAttributeMaxDynamicSharedMemorySize, SMEM_BYTES);

    wprep_kernel<<<24, 256>>>(Wf, Wg, Wh);

    proj_mma_kernel<<<BATCH * NTOK / PROWS, 128>>>(x, bf, bg, bh);

    dim3 agrid(NTOK / QT, BATCH, SPLITS);
    attn_kernel<<<agrid, NT, SMEM_BYTES>>>();

    outc_kernel<<<BATCH * NTOK * 32 / 256, 256>>>(x, Wo, bo, gamma, out);
}